// round 8
// baseline (speedup 1.0000x reference)
#include <cuda_runtime.h>
#include <cuda_bf16.h>
#include <cstdint>

typedef unsigned long long ull;

#define NB 256
#define NT 512
#define NH 128
#define NG3 384

// ---------------- static scratch ----------------
__device__ float g_gx[(size_t)NB * NT * NG3];
__device__ float g_hseq[(size_t)NB * NT * NH];

// ---------------- helpers ----------------
__device__ __forceinline__ uint32_t smem_u32(const void* p) {
    uint32_t a;
    asm("{ .reg .u64 t; cvta.to.shared.u64 t, %1; cvt.u32.u64 %0, t; }" : "=r"(a) : "l"(p));
    return a;
}
// xor-swizzled byte offset for a [128][K] bf16 tile: 16B chunks permuted by row&7
__device__ __forceinline__ int swoff(int row, int k, int K) {
    return row * K * 2 + ((((k >> 3) ^ (row & 7)) << 4) | ((k & 7) << 1));
}
__device__ __forceinline__ uint32_t bf2_bits(float a, float b) {
    __nv_bfloat162 h = __floats2bfloat162_rn(a, b);
    return *reinterpret_cast<uint32_t*>(&h);
}
__device__ __forceinline__ ull ffma2(ull a, ull b, ull c) {
    ull d;
    asm("fma.rn.f32x2 %0, %1, %2, %3;" : "=l"(d) : "l"(a), "l"(b), "l"(c));
    return d;
}
__device__ __forceinline__ float f32x2_sum(ull a) {
    float lo, hi;
    asm("mov.b64 {%0, %1}, %2;" : "=f"(lo), "=f"(hi) : "l"(a));
    return lo + hi;
}
__device__ __forceinline__ ull pack2(float lo, float hi) {
    ull u;
    asm("mov.b64 %0, {%1, %2};" : "=l"(u) : "f"(lo), "f"(hi));
    return u;
}
__device__ __forceinline__ float tanhapx(float x) {
    float y;
    asm("tanh.approx.f32 %0, %1;" : "=f"(y) : "f"(x));
    return y;
}

__device__ __forceinline__ void ldsm_x4(uint32_t* r, uint32_t addr) {
    asm volatile("ldmatrix.sync.aligned.m8n8.x4.shared.b16 {%0,%1,%2,%3}, [%4];"
                 : "=r"(r[0]), "=r"(r[1]), "=r"(r[2]), "=r"(r[3]) : "r"(addr));
}
__device__ __forceinline__ void ldsm_x2(uint32_t* r, uint32_t addr) {
    asm volatile("ldmatrix.sync.aligned.m8n8.x2.shared.b16 {%0,%1}, [%2];"
                 : "=r"(r[0]), "=r"(r[1]) : "r"(addr));
}
__device__ __forceinline__ void mma_bf16(float* c, const uint32_t* a, const uint32_t* b) {
    asm volatile(
        "mma.sync.aligned.m16n8k16.row.col.f32.bf16.bf16.f32 "
        "{%0,%1,%2,%3}, {%4,%5,%6,%7}, {%8,%9}, {%0,%1,%2,%3};"
        : "+f"(c[0]), "+f"(c[1]), "+f"(c[2]), "+f"(c[3])
        : "r"(a[0]), "r"(a[1]), "r"(a[2]), "r"(a[3]), "r"(b[0]), "r"(b[1]));
}

// ---------------- gx GEMM: g_gx[m,384] = A[m,K] @ W^T + b_ih ----------------
// 3-product split-bf16 emulation on mma.sync. CTA tile 128x128, full K in smem.
// (unchanged from the 2124us build)
template <int K>
__global__ __launch_bounds__(256, 1)
void gemm_mma(const float* __restrict__ A, const float* __restrict__ W,
              const float* __restrict__ bih) {
    extern __shared__ char sm[];
    constexpr int TILE = 128 * K * 2;
    char* Ahi = sm;
    char* Alo = Ahi + TILE;
    char* Whi = Alo + TILE;
    char* Wlo = Whi + TILE;

    const int tid = threadIdx.x;
    const int wid = tid >> 5, lane = tid & 31;
    const int mb = blockIdx.x, nb = blockIdx.y;
    const int warp_m = wid >> 2;
    const int warp_n = wid & 3;

    {
        const float4* Ag = reinterpret_cast<const float4*>(A + (size_t)mb * 128 * K);
        #pragma unroll
        for (int p = 0; p < (128 * K / 4) / 256; ++p) {
            int idx = tid + p * 256;
            int m = idx / (K / 4);
            int k = (idx % (K / 4)) * 4;
            float4 v = Ag[idx];
            float h0 = __bfloat162float(__float2bfloat16(v.x));
            float h1 = __bfloat162float(__float2bfloat16(v.y));
            float h2 = __bfloat162float(__float2bfloat16(v.z));
            float h3 = __bfloat162float(__float2bfloat16(v.w));
            uint2 hi = make_uint2(bf2_bits(v.x, v.y), bf2_bits(v.z, v.w));
            uint2 lo = make_uint2(bf2_bits(v.x - h0, v.y - h1), bf2_bits(v.z - h2, v.w - h3));
            int sw = swoff(m, k, K);
            *reinterpret_cast<uint2*>(Ahi + sw) = hi;
            *reinterpret_cast<uint2*>(Alo + sw) = lo;
        }
    }
    {
        const float4* Wg = reinterpret_cast<const float4*>(W + (size_t)nb * 128 * K);
        #pragma unroll
        for (int p = 0; p < (128 * K / 4) / 256; ++p) {
            int idx = tid + p * 256;
            int n = idx / (K / 4);
            int k = (idx % (K / 4)) * 4;
            float4 v = Wg[idx];
            float h0 = __bfloat162float(__float2bfloat16(v.x));
            float h1 = __bfloat162float(__float2bfloat16(v.y));
            float h2 = __bfloat162float(__float2bfloat16(v.z));
            float h3 = __bfloat162float(__float2bfloat16(v.w));
            uint2 hi = make_uint2(bf2_bits(v.x, v.y), bf2_bits(v.z, v.w));
            uint2 lo = make_uint2(bf2_bits(v.x - h0, v.y - h1), bf2_bits(v.z - h2, v.w - h3));
            int sw = swoff(n, k, K);
            *reinterpret_cast<uint2*>(Whi + sw) = hi;
            *reinterpret_cast<uint2*>(Wlo + sw) = lo;
        }
    }
    __syncthreads();

    float acc[4][4][4];
    #pragma unroll
    for (int i = 0; i < 4; ++i)
        #pragma unroll
        for (int j = 0; j < 4; ++j)
            #pragma unroll
            for (int q = 0; q < 4; ++q) acc[i][j][q] = 0.f;

    const char* Abufs[3] = { Ahi, Alo, Ahi };
    const char* Wbufs[3] = { Wlo, Whi, Whi };

    #pragma unroll
    for (int s = 0; s < 3; ++s) {
        const char* Ab = Abufs[s];
        const char* Wb = Wbufs[s];
        #pragma unroll
        for (int kk = 0; kk < K / 16; ++kk) {
            const int kb = kk * 16;
            uint32_t af[4][4], bf[4][2];
            #pragma unroll
            for (int mf = 0; mf < 4; ++mf) {
                int row = warp_m * 64 + mf * 16 + (lane & 15);
                ldsm_x4(af[mf], smem_u32(Ab + swoff(row, kb + (lane >> 4) * 8, K)));
            }
            #pragma unroll
            for (int nf = 0; nf < 4; ++nf) {
                int rn = warp_n * 32 + nf * 8 + (lane & 7);
                ldsm_x2(bf[nf], smem_u32(Wb + swoff(rn, kb + ((lane >> 3) & 1) * 8, K)));
            }
            #pragma unroll
            for (int mf = 0; mf < 4; ++mf)
                #pragma unroll
                for (int nf = 0; nf < 4; ++nf)
                    mma_bf16(acc[mf][nf], af[mf], bf[nf]);
        }
    }

    const int gr = lane >> 2, gc = (lane & 3) * 2;
    float bv[4][2];
    #pragma unroll
    for (int nf = 0; nf < 4; ++nf) {
        int col = nb * 128 + warp_n * 32 + nf * 8 + gc;
        bv[nf][0] = bih[col];
        bv[nf][1] = bih[col + 1];
    }
    #pragma unroll
    for (int mf = 0; mf < 4; ++mf) {
        int m0 = mb * 128 + warp_m * 64 + mf * 16 + gr;
        #pragma unroll
        for (int nf = 0; nf < 4; ++nf) {
            int col = nb * 128 + warp_n * 32 + nf * 8 + gc;
            float2 v0 = make_float2(acc[mf][nf][0] + bv[nf][0], acc[mf][nf][1] + bv[nf][1]);
            float2 v1 = make_float2(acc[mf][nf][2] + bv[nf][0], acc[mf][nf][3] + bv[nf][1]);
            *reinterpret_cast<float2*>(g_gx + (size_t)m0 * NG3 + col) = v0;
            *reinterpret_cast<float2*>(g_gx + (size_t)(m0 + 8) * NG3 + col) = v1;
        }
    }
}

// ---------------- GRU scan: k-split, 768 threads, 24 warps/SM ----------------
// Threads 0-383: k[0:64) of rows 0-383; threads 384-767: k[64:128).
// Partial dots land in smem; epilogue threads (tid<256) sum halves + gates.
__global__ __launch_bounds__(768, 1)
void gru_scan_kernel(const float* __restrict__ whh, const float* __restrict__ bhh) {
    __shared__ __align__(16) float h0s[NH];
    __shared__ __align__(16) float h1s[NH];
    __shared__ float accs[2 * 2 * 384];       // [batch][khalf][row]

    const int tid = threadIdx.x;
    const int kh  = (tid >= 384) ? 1 : 0;
    const int row = tid - kh * 384;
    const int b0  = blockIdx.x * 2;

    // half W_hh row -> 32 f32x2 registers
    ull wreg[32];
    {
        const float4* wp = reinterpret_cast<const float4*>(whh + (size_t)row * NH + kh * 64);
        #pragma unroll
        for (int q = 0; q < 16; ++q) {
            float4 v = wp[q];
            wreg[2 * q]     = pack2(v.x, v.y);
            wreg[2 * q + 1] = pack2(v.z, v.w);
        }
    }

    const int ub = tid >> 7, uj = tid & 127;   // epilogue mapping (tid<256)
    const float* gp   = g_gx   + ((size_t)(b0 + ub) * NT) * NG3 + uj;
    float*       hout = g_hseq + ((size_t)(b0 + ub) * NT) * NH  + uj;
    float br = 0.f, bz = 0.f, bn = 0.f;
    float gr = 0.f, gz = 0.f, gn = 0.f, hprev = 0.f;
    if (tid < 256) {
        if (ub == 0) h0s[uj] = 0.f; else h1s[uj] = 0.f;
        br = bhh[uj]; bz = bhh[128 + uj]; bn = bhh[256 + uj];
        gr = gp[0]; gz = gp[128]; gn = gp[256];
    }
    __syncthreads();

    const ulonglong2* p0 = reinterpret_cast<const ulonglong2*>(h0s + kh * 64);
    const ulonglong2* p1 = reinterpret_cast<const ulonglong2*>(h1s + kh * 64);

    for (int t = 0; t < NT; ++t) {
        ull a0 = 0ULL, a1 = 0ULL;
        #pragma unroll
        for (int q = 0; q < 16; ++q) {
            ulonglong2 v0 = p0[q];
            ulonglong2 v1 = p1[q];
            a0 = ffma2(wreg[2 * q],     v0.x, a0);
            a0 = ffma2(wreg[2 * q + 1], v0.y, a0);
            a1 = ffma2(wreg[2 * q],     v1.x, a1);
            a1 = ffma2(wreg[2 * q + 1], v1.y, a1);
        }
        accs[tid]        = f32x2_sum(a0);      // [0][kh][row]
        accs[768 + tid]  = f32x2_sum(a1);      // [1][kh][row]
        __syncthreads();

        if (tid < 256) {
            const float* ac = accs + ub * 768;
            float ar = ac[uj]       + ac[384 + uj];
            float az = ac[128 + uj] + ac[384 + 128 + uj];
            float an = ac[256 + uj] + ac[384 + 256 + uj];
            float r = 0.5f * tanhapx(0.5f * (gr + ar + br)) + 0.5f;
            float z = 0.5f * tanhapx(0.5f * (gz + az + bz)) + 0.5f;
            float n = tanhapx(gn + r * (an + bn));
            float hn = n + z * (hprev - n);
            hprev = hn;
            hout[(size_t)t * NH] = hn;
            if (ub == 0) h0s[uj] = hn; else h1s[uj] = hn;
            if (t + 1 < NT) {
                const float* g2 = gp + (size_t)(t + 1) * NG3;
                gr = g2[0]; gz = g2[128]; gn = g2[256];
            }
        }
        __syncthreads();
    }
}

// ---------------- final FC ----------------
__global__ void fc_kernel(const float* __restrict__ fcw, const float* __restrict__ fcb,
                          float* __restrict__ out) {
    int b = blockIdx.x;
    int w = threadIdx.x >> 5;
    int lane = threadIdx.x & 31;
    if (w >= 6) return;
    const float* last = g_hseq + ((size_t)b * NT + NT - 1) * NH;
    float s = 0.f;
    #pragma unroll
    for (int k = 0; k < 4; ++k) {
        int j = lane + 32 * k;
        s += last[j] * fcw[w * NH + j];
    }
    #pragma unroll
    for (int o = 16; o; o >>= 1) s += __shfl_down_sync(0xffffffffu, s, o);
    if (lane == 0) out[b * 6 + w] = s + fcb[w];
}

// ---------------- launch ----------------
extern "C" void kernel_launch(void* const* d_in, const int* in_sizes, int n_in,
                              void* d_out, int out_size) {
    const float* x    = (const float*)d_in[0];
    const float* wih0 = (const float*)d_in[1];
    const float* wih1 = (const float*)d_in[2];
    const float* wih2 = (const float*)d_in[3];
    const float* whh  = (const float*)d_in[4];
    const float* bih  = (const float*)d_in[5];
    const float* bhh  = (const float*)d_in[6];
    const float* fcw  = (const float*)d_in[7];
    const float* fcb  = (const float*)d_in[8];
    float* out = (float*)d_out;

    constexpr int SMEM64  = 4 * 128 * 64 * 2;
    constexpr int SMEM128 = 4 * 128 * 128 * 2;
    cudaFuncSetAttribute(gemm_mma<64>,  cudaFuncAttributeMaxDynamicSharedMemorySize, SMEM64);
    cudaFuncSetAttribute(gemm_mma<128>, cudaFuncAttributeMaxDynamicSharedMemorySize, SMEM128);

    float* g_hseq_ptr = nullptr;
    cudaGetSymbolAddress((void**)&g_hseq_ptr, g_hseq);

    dim3 ggrid(NB * NT / 128, 3);

    gemm_mma<64><<<ggrid, 256, SMEM64>>>(x, wih0, bih + 0 * NG3);                 // 1
    gru_scan_kernel<<<NB / 2, 768>>>(whh + 0 * NG3 * NH, bhh + 0 * NG3);          // 2
    gemm_mma<128><<<ggrid, 256, SMEM128>>>(g_hseq_ptr, wih1, bih + 1 * NG3);      // 3
    gru_scan_kernel<<<NB / 2, 768>>>(whh + 1 * NG3 * NH, bhh + 1 * NG3);          // 4
    gemm_mma<128><<<ggrid, 256, SMEM128>>>(g_hseq_ptr, wih2, bih + 2 * NG3);      // 5
    gru_scan_kernel<<<NB / 2, 768>>>(whh + 2 * NG3 * NH, bhh + 2 * NG3);          // 6 (ncu -s 5 target)
    fc_kernel<<<NB, 192>>>(fcw, fcb, out);                                        // 7
}

// round 9
// speedup vs baseline: 1.3105x; 1.3105x over previous
#include <cuda_runtime.h>
#include <cuda_bf16.h>
#include <cstdint>

typedef unsigned long long ull;

#define NB 256
#define NT 512
#define NH 128
#define NG3 384

// ---------------- static scratch ----------------
__device__ float g_gx[(size_t)NB * NT * NG3];
__device__ float g_hseq[(size_t)NB * NT * NH];

// ---------------- helpers ----------------
__device__ __forceinline__ uint32_t smem_u32(const void* p) {
    uint32_t a;
    asm("{ .reg .u64 t; cvta.to.shared.u64 t, %1; cvt.u32.u64 %0, t; }" : "=r"(a) : "l"(p));
    return a;
}
// xor-swizzled byte offset for a [128][K] bf16 tile: 16B chunks permuted by row&7
__device__ __forceinline__ int swoff(int row, int k, int K) {
    return row * K * 2 + ((((k >> 3) ^ (row & 7)) << 4) | ((k & 7) << 1));
}
__device__ __forceinline__ uint32_t bf2_bits(float a, float b) {
    __nv_bfloat162 h = __floats2bfloat162_rn(a, b);
    return *reinterpret_cast<uint32_t*>(&h);
}
__device__ __forceinline__ ull ffma2(ull a, ull b, ull c) {
    ull d;
    asm("fma.rn.f32x2 %0, %1, %2, %3;" : "=l"(d) : "l"(a), "l"(b), "l"(c));
    return d;
}
__device__ __forceinline__ float f32x2_sum(ull a) {
    float lo, hi;
    asm("mov.b64 {%0, %1}, %2;" : "=f"(lo), "=f"(hi) : "l"(a));
    return lo + hi;
}
__device__ __forceinline__ ull pack2(float lo, float hi) {
    ull u;
    asm("mov.b64 %0, {%1, %2};" : "=l"(u) : "f"(lo), "f"(hi));
    return u;
}
__device__ __forceinline__ float tanhapx(float x) {
    float y;
    asm("tanh.approx.f32 %0, %1;" : "=f"(y) : "f"(x));
    return y;
}

__device__ __forceinline__ void ldsm_x4(uint32_t* r, uint32_t addr) {
    asm volatile("ldmatrix.sync.aligned.m8n8.x4.shared.b16 {%0,%1,%2,%3}, [%4];"
                 : "=r"(r[0]), "=r"(r[1]), "=r"(r[2]), "=r"(r[3]) : "r"(addr));
}
__device__ __forceinline__ void ldsm_x2(uint32_t* r, uint32_t addr) {
    asm volatile("ldmatrix.sync.aligned.m8n8.x2.shared.b16 {%0,%1}, [%2];"
                 : "=r"(r[0]), "=r"(r[1]) : "r"(addr));
}
__device__ __forceinline__ void mma_bf16(float* c, const uint32_t* a, const uint32_t* b) {
    asm volatile(
        "mma.sync.aligned.m16n8k16.row.col.f32.bf16.bf16.f32 "
        "{%0,%1,%2,%3}, {%4,%5,%6,%7}, {%8,%9}, {%0,%1,%2,%3};"
        : "+f"(c[0]), "+f"(c[1]), "+f"(c[2]), "+f"(c[3])
        : "r"(a[0]), "r"(a[1]), "r"(a[2]), "r"(a[3]), "r"(b[0]), "r"(b[1]));
}

// ---------------- gx GEMM: g_gx[m,384] = A[m,K] @ W^T + b_ih ----------------
// 3-product split-bf16 emulation on mma.sync. CTA tile 128x128, full K in smem.
// 512 threads: 4x4 warp grid, 32x32 warp tile (was 256 thr / 64x32).
template <int K>
__global__ __launch_bounds__(512, 1)
void gemm_mma(const float* __restrict__ A, const float* __restrict__ W,
              const float* __restrict__ bih) {
    extern __shared__ char sm[];
    constexpr int TILE = 128 * K * 2;
    char* Ahi = sm;
    char* Alo = Ahi + TILE;
    char* Whi = Alo + TILE;
    char* Wlo = Whi + TILE;

    const int tid = threadIdx.x;
    const int wid = tid >> 5, lane = tid & 31;
    const int mb = blockIdx.x, nb = blockIdx.y;
    const int warp_m = wid >> 2;        // 0..3  (32 rows each)
    const int warp_n = wid & 3;         // 0..3  (32 cols each)

    // ---- load + split A tile ----
    {
        const float4* Ag = reinterpret_cast<const float4*>(A + (size_t)mb * 128 * K);
        #pragma unroll
        for (int p = 0; p < (128 * K / 4) / 512; ++p) {
            int idx = tid + p * 512;
            int m = idx / (K / 4);
            int k = (idx % (K / 4)) * 4;
            float4 v = Ag[idx];
            float h0 = __bfloat162float(__float2bfloat16(v.x));
            float h1 = __bfloat162float(__float2bfloat16(v.y));
            float h2 = __bfloat162float(__float2bfloat16(v.z));
            float h3 = __bfloat162float(__float2bfloat16(v.w));
            uint2 hi = make_uint2(bf2_bits(v.x, v.y), bf2_bits(v.z, v.w));
            uint2 lo = make_uint2(bf2_bits(v.x - h0, v.y - h1), bf2_bits(v.z - h2, v.w - h3));
            int sw = swoff(m, k, K);
            *reinterpret_cast<uint2*>(Ahi + sw) = hi;
            *reinterpret_cast<uint2*>(Alo + sw) = lo;
        }
    }
    // ---- load + split W tile (rows nb*128 .. +128 of [384][K]) ----
    {
        const float4* Wg = reinterpret_cast<const float4*>(W + (size_t)nb * 128 * K);
        #pragma unroll
        for (int p = 0; p < (128 * K / 4) / 512; ++p) {
            int idx = tid + p * 512;
            int n = idx / (K / 4);
            int k = (idx % (K / 4)) * 4;
            float4 v = Wg[idx];
            float h0 = __bfloat162float(__float2bfloat16(v.x));
            float h1 = __bfloat162float(__float2bfloat16(v.y));
            float h2 = __bfloat162float(__float2bfloat16(v.z));
            float h3 = __bfloat162float(__float2bfloat16(v.w));
            uint2 hi = make_uint2(bf2_bits(v.x, v.y), bf2_bits(v.z, v.w));
            uint2 lo = make_uint2(bf2_bits(v.x - h0, v.y - h1), bf2_bits(v.z - h2, v.w - h3));
            int sw = swoff(n, k, K);
            *reinterpret_cast<uint2*>(Whi + sw) = hi;
            *reinterpret_cast<uint2*>(Wlo + sw) = lo;
        }
    }
    __syncthreads();

    float acc[2][4][4];                 // [mf][nf][quad]
    #pragma unroll
    for (int i = 0; i < 2; ++i)
        #pragma unroll
        for (int j = 0; j < 4; ++j)
            #pragma unroll
            for (int q = 0; q < 4; ++q) acc[i][j][q] = 0.f;

    const char* Abufs[3] = { Ahi, Alo, Ahi };   // (Ahi*Wlo)+(Alo*Whi)+(Ahi*Whi)
    const char* Wbufs[3] = { Wlo, Whi, Whi };

    #pragma unroll
    for (int s = 0; s < 3; ++s) {
        const char* Ab = Abufs[s];
        const char* Wb = Wbufs[s];
        #pragma unroll
        for (int kk = 0; kk < K / 16; ++kk) {
            const int kb = kk * 16;
            uint32_t af[2][4], bf[4][2];
            #pragma unroll
            for (int mf = 0; mf < 2; ++mf) {
                int row = warp_m * 32 + mf * 16 + (lane & 15);
                ldsm_x4(af[mf], smem_u32(Ab + swoff(row, kb + (lane >> 4) * 8, K)));
            }
            #pragma unroll
            for (int nf = 0; nf < 4; ++nf) {
                int rn = warp_n * 32 + nf * 8 + (lane & 7);
                ldsm_x2(bf[nf], smem_u32(Wb + swoff(rn, kb + ((lane >> 3) & 1) * 8, K)));
            }
            #pragma unroll
            for (int mf = 0; mf < 2; ++mf)
                #pragma unroll
                for (int nf = 0; nf < 4; ++nf)
                    mma_bf16(acc[mf][nf], af[mf], bf[nf]);
        }
    }

    const int gr = lane >> 2, gc = (lane & 3) * 2;
    float bv[4][2];
    #pragma unroll
    for (int nf = 0; nf < 4; ++nf) {
        int col = nb * 128 + warp_n * 32 + nf * 8 + gc;
        bv[nf][0] = bih[col];
        bv[nf][1] = bih[col + 1];
    }
    #pragma unroll
    for (int mf = 0; mf < 2; ++mf) {
        int m0 = mb * 128 + warp_m * 32 + mf * 16 + gr;
        #pragma unroll
        for (int nf = 0; nf < 4; ++nf) {
            int col = nb * 128 + warp_n * 32 + nf * 8 + gc;
            float2 v0 = make_float2(acc[mf][nf][0] + bv[nf][0], acc[mf][nf][1] + bv[nf][1]);
            float2 v1 = make_float2(acc[mf][nf][2] + bv[nf][0], acc[mf][nf][3] + bv[nf][1]);
            *reinterpret_cast<float2*>(g_gx + (size_t)m0 * NG3 + col) = v0;
            *reinterpret_cast<float2*>(g_gx + (size_t)(m0 + 8) * NG3 + col) = v1;
        }
    }
}

// ---------------- GRU scan: R7 structure (384 thr, 2 batches, W in regs) ----------------
// Changes vs R7: gx(t+1) prefetch hoisted above the matvec; STS h before STG hout.
__global__ __launch_bounds__(384, 1)
void gru_scan_kernel(const float* __restrict__ whh, const float* __restrict__ bhh) {
    __shared__ __align__(16) float h0s[NH];
    __shared__ __align__(16) float h1s[NH];
    __shared__ float accs[2 * NG3];

    int tid = threadIdx.x;
    int b0 = blockIdx.x * 2;

    ull wreg[64];
    {
        const float4* wp = reinterpret_cast<const float4*>(whh + (size_t)tid * NH);
        #pragma unroll
        for (int q = 0; q < 32; ++q) {
            float4 v = wp[q];
            wreg[2 * q]     = pack2(v.x, v.y);
            wreg[2 * q + 1] = pack2(v.z, v.w);
        }
    }
    float bias = bhh[tid];

    int ub = tid >> 7, uj = tid & 127;
    const float* gp   = g_gx   + ((size_t)(b0 + ub) * NT) * NG3 + uj;
    float*       hout = g_hseq + ((size_t)(b0 + ub) * NT) * NH  + uj;
    float gr = 0.f, gz = 0.f, gn = 0.f, hprev = 0.f;
    if (tid < 256) {
        if (ub == 0) h0s[uj] = 0.f; else h1s[uj] = 0.f;
        gr = gp[0]; gz = gp[128]; gn = gp[256];
    }
    __syncthreads();

    const ulonglong2* h0p = reinterpret_cast<const ulonglong2*>(h0s);
    const ulonglong2* h1p = reinterpret_cast<const ulonglong2*>(h1s);

    for (int t = 0; t < NT; ++t) {
        // gx(t+1) prefetch issued under the matvec (off the epilogue critical path)
        float ngr = 0.f, ngz = 0.f, ngn = 0.f;
        if (tid < 256 && t + 1 < NT) {
            const float* g2 = gp + (size_t)(t + 1) * NG3;
            ngr = __ldg(g2); ngz = __ldg(g2 + 128); ngn = __ldg(g2 + 256);
        }

        ull a0 = 0ULL, a1 = 0ULL;
        #pragma unroll
        for (int q = 0; q < 32; ++q) {
            ulonglong2 v0 = h0p[q];
            ulonglong2 v1 = h1p[q];
            a0 = ffma2(wreg[2 * q],     v0.x, a0);
            a0 = ffma2(wreg[2 * q + 1], v0.y, a0);
            a1 = ffma2(wreg[2 * q],     v1.x, a1);
            a1 = ffma2(wreg[2 * q + 1], v1.y, a1);
        }
        accs[tid]       = f32x2_sum(a0) + bias;
        accs[NG3 + tid] = f32x2_sum(a1) + bias;
        __syncthreads();

        if (tid < 256) {
            const float* ac = accs + ub * NG3;
            float r = 0.5f * tanhapx(0.5f * (gr + ac[uj]))       + 0.5f;
            float z = 0.5f * tanhapx(0.5f * (gz + ac[128 + uj])) + 0.5f;
            float n = tanhapx(gn + r * ac[256 + uj]);
            float hn = n + z * (hprev - n);
            hprev = hn;
            if (ub == 0) h0s[uj] = hn; else h1s[uj] = hn;   // STS first: gates next matvec
            hout[(size_t)t * NH] = hn;                       // STG after
            gr = ngr; gz = ngz; gn = ngn;
        }
        __syncthreads();
    }
}

// ---------------- final FC ----------------
__global__ void fc_kernel(const float* __restrict__ fcw, const float* __restrict__ fcb,
                          float* __restrict__ out) {
    int b = blockIdx.x;
    int w = threadIdx.x >> 5;
    int lane = threadIdx.x & 31;
    if (w >= 6) return;
    const float* last = g_hseq + ((size_t)b * NT + NT - 1) * NH;
    float s = 0.f;
    #pragma unroll
    for (int k = 0; k < 4; ++k) {
        int j = lane + 32 * k;
        s += last[j] * fcw[w * NH + j];
    }
    #pragma unroll
    for (int o = 16; o; o >>= 1) s += __shfl_down_sync(0xffffffffu, s, o);
    if (lane == 0) out[b * 6 + w] = s + fcb[w];
}

// ---------------- launch ----------------
extern "C" void kernel_launch(void* const* d_in, const int* in_sizes, int n_in,
                              void* d_out, int out_size) {
    const float* x    = (const float*)d_in[0];
    const float* wih0 = (const float*)d_in[1];
    const float* wih1 = (const float*)d_in[2];
    const float* wih2 = (const float*)d_in[3];
    const float* whh  = (const float*)d_in[4];
    const float* bih  = (const float*)d_in[5];
    const float* bhh  = (const float*)d_in[6];
    const float* fcw  = (const float*)d_in[7];
    const float* fcb  = (const float*)d_in[8];
    float* out = (float*)d_out;

    constexpr int SMEM64  = 4 * 128 * 64 * 2;
    constexpr int SMEM128 = 4 * 128 * 128 * 2;
    cudaFuncSetAttribute(gemm_mma<64>,  cudaFuncAttributeMaxDynamicSharedMemorySize, SMEM64);
    cudaFuncSetAttribute(gemm_mma<128>, cudaFuncAttributeMaxDynamicSharedMemorySize, SMEM128);

    float* g_hseq_ptr = nullptr;
    cudaGetSymbolAddress((void**)&g_hseq_ptr, g_hseq);

    dim3 ggrid(NB * NT / 128, 3);

    gemm_mma<64><<<ggrid, 512, SMEM64>>>(x, wih0, bih + 0 * NG3);                 // 1
    gru_scan_kernel<<<NB / 2, 384>>>(whh + 0 * NG3 * NH, bhh + 0 * NG3);          // 2
    gemm_mma<128><<<ggrid, 512, SMEM128>>>(g_hseq_ptr, wih1, bih + 1 * NG3);      // 3
    gru_scan_kernel<<<NB / 2, 384>>>(whh + 1 * NG3 * NH, bhh + 1 * NG3);          // 4
    gemm_mma<128><<<ggrid, 512, SMEM128>>>(g_hseq_ptr, wih2, bih + 2 * NG3);      // 5
    gru_scan_kernel<<<NB / 2, 384>>>(whh + 2 * NG3 * NH, bhh + 2 * NG3);          // 6 (ncu -s 5 target)
    fc_kernel<<<NB, 192>>>(fcw, fcb, out);                                        // 7
}

// round 10
// speedup vs baseline: 1.4965x; 1.1419x over previous
#include <cuda_runtime.h>
#include <cuda_bf16.h>
#include <cstdint>

typedef unsigned long long ull;

#define NB 256
#define NT 512
#define NH 128
#define NG3 384

// ---------------- static scratch ----------------
__device__ float g_gx[(size_t)NB * NT * NG3];
__device__ float g_hseq[(size_t)NB * NT * NH];

// ---------------- helpers ----------------
__device__ __forceinline__ uint32_t smem_u32(const void* p) {
    uint32_t a;
    asm("{ .reg .u64 t; cvta.to.shared.u64 t, %1; cvt.u32.u64 %0, t; }" : "=r"(a) : "l"(p));
    return a;
}
// xor-swizzled byte offset for a [128][K] bf16 tile: 16B chunks permuted by row&7
__device__ __forceinline__ int swoff(int row, int k, int K) {
    return row * K * 2 + ((((k >> 3) ^ (row & 7)) << 4) | ((k & 7) << 1));
}
__device__ __forceinline__ uint32_t bf2_bits(float a, float b) {
    __nv_bfloat162 h = __floats2bfloat162_rn(a, b);
    return *reinterpret_cast<uint32_t*>(&h);
}
__device__ __forceinline__ ull ffma2(ull a, ull b, ull c) {
    ull d;
    asm("fma.rn.f32x2 %0, %1, %2, %3;" : "=l"(d) : "l"(a), "l"(b), "l"(c));
    return d;
}
__device__ __forceinline__ float f32x2_sum(ull a) {
    float lo, hi;
    asm("mov.b64 {%0, %1}, %2;" : "=f"(lo), "=f"(hi) : "l"(a));
    return lo + hi;
}
__device__ __forceinline__ ull pack2(float lo, float hi) {
    ull u;
    asm("mov.b64 %0, {%1, %2};" : "=l"(u) : "f"(lo), "f"(hi));
    return u;
}
__device__ __forceinline__ float tanhapx(float x) {
    float y;
    asm("tanh.approx.f32 %0, %1;" : "=f"(y) : "f"(x));
    return y;
}

__device__ __forceinline__ void ldsm_x4(uint32_t* r, uint32_t addr) {
    asm volatile("ldmatrix.sync.aligned.m8n8.x4.shared.b16 {%0,%1,%2,%3}, [%4];"
                 : "=r"(r[0]), "=r"(r[1]), "=r"(r[2]), "=r"(r[3]) : "r"(addr));
}
__device__ __forceinline__ void ldsm_x2(uint32_t* r, uint32_t addr) {
    asm volatile("ldmatrix.sync.aligned.m8n8.x2.shared.b16 {%0,%1}, [%2];"
                 : "=r"(r[0]), "=r"(r[1]) : "r"(addr));
}
__device__ __forceinline__ void mma_bf16(float* c, const uint32_t* a, const uint32_t* b) {
    asm volatile(
        "mma.sync.aligned.m16n8k16.row.col.f32.bf16.bf16.f32 "
        "{%0,%1,%2,%3}, {%4,%5,%6,%7}, {%8,%9}, {%0,%1,%2,%3};"
        : "+f"(c[0]), "+f"(c[1]), "+f"(c[2]), "+f"(c[3])
        : "r"(a[0]), "r"(a[1]), "r"(a[2]), "r"(a[3]), "r"(b[0]), "r"(b[1]));
}

// ---------------- gx GEMM: g_gx[m,384] = A[m,K] @ W^T + b_ih ----------------
// (exact R7 version: 256 threads, 2x4 warp grid, 64x32 warp tile)
template <int K>
__global__ __launch_bounds__(256, 1)
void gemm_mma(const float* __restrict__ A, const float* __restrict__ W,
              const float* __restrict__ bih) {
    extern __shared__ char sm[];
    constexpr int TILE = 128 * K * 2;
    char* Ahi = sm;
    char* Alo = Ahi + TILE;
    char* Whi = Alo + TILE;
    char* Wlo = Whi + TILE;

    const int tid = threadIdx.x;
    const int wid = tid >> 5, lane = tid & 31;
    const int mb = blockIdx.x, nb = blockIdx.y;
    const int warp_m = wid >> 2;
    const int warp_n = wid & 3;

    {
        const float4* Ag = reinterpret_cast<const float4*>(A + (size_t)mb * 128 * K);
        #pragma unroll
        for (int p = 0; p < (128 * K / 4) / 256; ++p) {
            int idx = tid + p * 256;
            int m = idx / (K / 4);
            int k = (idx % (K / 4)) * 4;
            float4 v = Ag[idx];
            float h0 = __bfloat162float(__float2bfloat16(v.x));
            float h1 = __bfloat162float(__float2bfloat16(v.y));
            float h2 = __bfloat162float(__float2bfloat16(v.z));
            float h3 = __bfloat162float(__float2bfloat16(v.w));
            uint2 hi = make_uint2(bf2_bits(v.x, v.y), bf2_bits(v.z, v.w));
            uint2 lo = make_uint2(bf2_bits(v.x - h0, v.y - h1), bf2_bits(v.z - h2, v.w - h3));
            int sw = swoff(m, k, K);
            *reinterpret_cast<uint2*>(Ahi + sw) = hi;
            *reinterpret_cast<uint2*>(Alo + sw) = lo;
        }
    }
    {
        const float4* Wg = reinterpret_cast<const float4*>(W + (size_t)nb * 128 * K);
        #pragma unroll
        for (int p = 0; p < (128 * K / 4) / 256; ++p) {
            int idx = tid + p * 256;
            int n = idx / (K / 4);
            int k = (idx % (K / 4)) * 4;
            float4 v = Wg[idx];
            float h0 = __bfloat162float(__float2bfloat16(v.x));
            float h1 = __bfloat162float(__float2bfloat16(v.y));
            float h2 = __bfloat162float(__float2bfloat16(v.z));
            float h3 = __bfloat162float(__float2bfloat16(v.w));
            uint2 hi = make_uint2(bf2_bits(v.x, v.y), bf2_bits(v.z, v.w));
            uint2 lo = make_uint2(bf2_bits(v.x - h0, v.y - h1), bf2_bits(v.z - h2, v.w - h3));
            int sw = swoff(n, k, K);
            *reinterpret_cast<uint2*>(Whi + sw) = hi;
            *reinterpret_cast<uint2*>(Wlo + sw) = lo;
        }
    }
    __syncthreads();

    float acc[4][4][4];
    #pragma unroll
    for (int i = 0; i < 4; ++i)
        #pragma unroll
        for (int j = 0; j < 4; ++j)
            #pragma unroll
            for (int q = 0; q < 4; ++q) acc[i][j][q] = 0.f;

    const char* Abufs[3] = { Ahi, Alo, Ahi };
    const char* Wbufs[3] = { Wlo, Whi, Whi };

    #pragma unroll
    for (int s = 0; s < 3; ++s) {
        const char* Ab = Abufs[s];
        const char* Wb = Wbufs[s];
        #pragma unroll
        for (int kk = 0; kk < K / 16; ++kk) {
            const int kb = kk * 16;
            uint32_t af[4][4], bf[4][2];
            #pragma unroll
            for (int mf = 0; mf < 4; ++mf) {
                int row = warp_m * 64 + mf * 16 + (lane & 15);
                ldsm_x4(af[mf], smem_u32(Ab + swoff(row, kb + (lane >> 4) * 8, K)));
            }
            #pragma unroll
            for (int nf = 0; nf < 4; ++nf) {
                int rn = warp_n * 32 + nf * 8 + (lane & 7);
                ldsm_x2(bf[nf], smem_u32(Wb + swoff(rn, kb + ((lane >> 3) & 1) * 8, K)));
            }
            #pragma unroll
            for (int mf = 0; mf < 4; ++mf)
                #pragma unroll
                for (int nf = 0; nf < 4; ++nf)
                    mma_bf16(acc[mf][nf], af[mf], bf[nf]);
        }
    }

    const int gr = lane >> 2, gc = (lane & 3) * 2;
    float bv[4][2];
    #pragma unroll
    for (int nf = 0; nf < 4; ++nf) {
        int col = nb * 128 + warp_n * 32 + nf * 8 + gc;
        bv[nf][0] = bih[col];
        bv[nf][1] = bih[col + 1];
    }
    #pragma unroll
    for (int mf = 0; mf < 4; ++mf) {
        int m0 = mb * 128 + warp_m * 64 + mf * 16 + gr;
        #pragma unroll
        for (int nf = 0; nf < 4; ++nf) {
            int col = nb * 128 + warp_n * 32 + nf * 8 + gc;
            float2 v0 = make_float2(acc[mf][nf][0] + bv[nf][0], acc[mf][nf][1] + bv[nf][1]);
            float2 v1 = make_float2(acc[mf][nf][2] + bv[nf][0], acc[mf][nf][3] + bv[nf][1]);
            *reinterpret_cast<float2*>(g_gx + (size_t)m0 * NG3 + col) = v0;
            *reinterpret_cast<float2*>(g_gx + (size_t)(m0 + 8) * NG3 + col) = v1;
        }
    }
}

// ---------------- GRU scan: warp-internal k-split (4x fewer LDS) ----------------
// 384 threads. Lane l of warp w: kseg = l&3 (32 of 128 k), rows w*32 + (l>>2)*4 + rr.
// Per step: 2 batch passes x (8 LDS.128 + 64 FFMA2), bfly-reduce over 4 ksegs,
// kseg-0 lanes write row sums as STS.128. Epilogue identical to the 2124us build.
#define HSEG 40   // padded segment stride (floats): bases hit banks 0/8/16/24
__global__ __launch_bounds__(384, 1)
void gru_scan_kernel(const float* __restrict__ whh, const float* __restrict__ bhh) {
    __shared__ __align__(16) float h0s[4 * HSEG];
    __shared__ __align__(16) float h1s[4 * HSEG];
    __shared__ __align__(16) float accs[2 * NG3];

    const int tid  = threadIdx.x;
    const int wid  = tid >> 5, lane = tid & 31;
    const int kseg = lane & 3;
    const int row0 = wid * 32 + (lane >> 2) * 4;   // 4 rows: row0..row0+3
    const int b0   = blockIdx.x * 2;

    // W regs: wreg[rr][q] = f32x2 of k-pair (kseg*32 + 2q, +1), q=0..15
    ull wreg[4][16];
    #pragma unroll
    for (int rr = 0; rr < 4; ++rr) {
        const float4* wp = reinterpret_cast<const float4*>(
            whh + (size_t)(row0 + rr) * NH + kseg * 32);
        #pragma unroll
        for (int f = 0; f < 8; ++f) {
            float4 v = wp[f];
            wreg[rr][2 * f]     = pack2(v.x, v.y);
            wreg[rr][2 * f + 1] = pack2(v.z, v.w);
        }
    }
    float bias[4];
    #pragma unroll
    for (int rr = 0; rr < 4; ++rr) bias[rr] = (kseg == 0) ? bhh[row0 + rr] : 0.f;

    // epilogue mapping (tid < 256): ub = batch lane, uj = unit
    const int ub = tid >> 7, uj = tid & 127;
    const int hoff = (uj >> 5) * HSEG + (uj & 31);
    const float* gp   = g_gx   + ((size_t)(b0 + ub) * NT) * NG3 + uj;
    float*       hout = g_hseq + ((size_t)(b0 + ub) * NT) * NH  + uj;
    float gr = 0.f, gz = 0.f, gn = 0.f, hprev = 0.f;
    if (tid < 256) {
        if (ub == 0) h0s[hoff] = 0.f; else h1s[hoff] = 0.f;
        gr = gp[0]; gz = gp[128]; gn = gp[256];
    }
    __syncthreads();

    const ulonglong2* p0 = reinterpret_cast<const ulonglong2*>(h0s + kseg * HSEG);
    const ulonglong2* p1 = reinterpret_cast<const ulonglong2*>(h1s + kseg * HSEG);

    for (int t = 0; t < NT; ++t) {
        float s0[4], s1[4];
        // ---- batch 0 pass ----
        {
            ull a[4] = {0ULL, 0ULL, 0ULL, 0ULL};
            #pragma unroll
            for (int j = 0; j < 8; ++j) {
                ulonglong2 v = p0[j];
                #pragma unroll
                for (int rr = 0; rr < 4; ++rr) {
                    a[rr] = ffma2(wreg[rr][2 * j],     v.x, a[rr]);
                    a[rr] = ffma2(wreg[rr][2 * j + 1], v.y, a[rr]);
                }
            }
            #pragma unroll
            for (int rr = 0; rr < 4; ++rr) {
                float s = f32x2_sum(a[rr]);
                s += __shfl_xor_sync(0xffffffffu, s, 1);
                s += __shfl_xor_sync(0xffffffffu, s, 2);
                s0[rr] = s + bias[rr];
            }
        }
        // ---- batch 1 pass ----
        {
            ull a[4] = {0ULL, 0ULL, 0ULL, 0ULL};
            #pragma unroll
            for (int j = 0; j < 8; ++j) {
                ulonglong2 v = p1[j];
                #pragma unroll
                for (int rr = 0; rr < 4; ++rr) {
                    a[rr] = ffma2(wreg[rr][2 * j],     v.x, a[rr]);
                    a[rr] = ffma2(wreg[rr][2 * j + 1], v.y, a[rr]);
                }
            }
            #pragma unroll
            for (int rr = 0; rr < 4; ++rr) {
                float s = f32x2_sum(a[rr]);
                s += __shfl_xor_sync(0xffffffffu, s, 1);
                s += __shfl_xor_sync(0xffffffffu, s, 2);
                s1[rr] = s + bias[rr];
            }
        }
        if (kseg == 0) {
            *reinterpret_cast<float4*>(accs + row0)       = make_float4(s0[0], s0[1], s0[2], s0[3]);
            *reinterpret_cast<float4*>(accs + NG3 + row0) = make_float4(s1[0], s1[1], s1[2], s1[3]);
        }
        __syncthreads();

        if (tid < 256) {
            const float* ac = accs + ub * NG3;
            float r = 0.5f * tanhapx(0.5f * (gr + ac[uj]))       + 0.5f;
            float z = 0.5f * tanhapx(0.5f * (gz + ac[128 + uj])) + 0.5f;
            float n = tanhapx(gn + r * ac[256 + uj]);
            float hn = n + z * (hprev - n);
            hprev = hn;
            hout[(size_t)t * NH] = hn;
            if (ub == 0) h0s[hoff] = hn; else h1s[hoff] = hn;
            if (t + 1 < NT) {
                const float* g2 = gp + (size_t)(t + 1) * NG3;
                gr = g2[0]; gz = g2[128]; gn = g2[256];
            }
        }
        __syncthreads();
    }
}

// ---------------- final FC ----------------
__global__ void fc_kernel(const float* __restrict__ fcw, const float* __restrict__ fcb,
                          float* __restrict__ out) {
    int b = blockIdx.x;
    int w = threadIdx.x >> 5;
    int lane = threadIdx.x & 31;
    if (w >= 6) return;
    const float* last = g_hseq + ((size_t)b * NT + NT - 1) * NH;
    float s = 0.f;
    #pragma unroll
    for (int k = 0; k < 4; ++k) {
        int j = lane + 32 * k;
        s += last[j] * fcw[w * NH + j];
    }
    #pragma unroll
    for (int o = 16; o; o >>= 1) s += __shfl_down_sync(0xffffffffu, s, o);
    if (lane == 0) out[b * 6 + w] = s + fcb[w];
}

// ---------------- launch ----------------
extern "C" void kernel_launch(void* const* d_in, const int* in_sizes, int n_in,
                              void* d_out, int out_size) {
    const float* x    = (const float*)d_in[0];
    const float* wih0 = (const float*)d_in[1];
    const float* wih1 = (const float*)d_in[2];
    const float* wih2 = (const float*)d_in[3];
    const float* whh  = (const float*)d_in[4];
    const float* bih  = (const float*)d_in[5];
    const float* bhh  = (const float*)d_in[6];
    const float* fcw  = (const float*)d_in[7];
    const float* fcb  = (const float*)d_in[8];
    float* out = (float*)d_out;

    constexpr int SMEM64  = 4 * 128 * 64 * 2;
    constexpr int SMEM128 = 4 * 128 * 128 * 2;
    cudaFuncSetAttribute(gemm_mma<64>,  cudaFuncAttributeMaxDynamicSharedMemorySize, SMEM64);
    cudaFuncSetAttribute(gemm_mma<128>, cudaFuncAttributeMaxDynamicSharedMemorySize, SMEM128);

    float* g_hseq_ptr = nullptr;
    cudaGetSymbolAddress((void**)&g_hseq_ptr, g_hseq);

    dim3 ggrid(NB * NT / 128, 3);

    gemm_mma<64><<<ggrid, 256, SMEM64>>>(x, wih0, bih + 0 * NG3);                 // 1
    gru_scan_kernel<<<NB / 2, 384>>>(whh + 0 * NG3 * NH, bhh + 0 * NG3);          // 2
    gemm_mma<128><<<ggrid, 256, SMEM128>>>(g_hseq_ptr, wih1, bih + 1 * NG3);      // 3
    gru_scan_kernel<<<NB / 2, 384>>>(whh + 1 * NG3 * NH, bhh + 1 * NG3);          // 4
    gemm_mma<128><<<ggrid, 256, SMEM128>>>(g_hseq_ptr, wih2, bih + 2 * NG3);      // 5
    gru_scan_kernel<<<NB / 2, 384>>>(whh + 2 * NG3 * NH, bhh + 2 * NG3);          // 6 (ncu -s 5 target)
    fc_kernel<<<NB, 192>>>(fcw, fcb, out);                                        // 7
}